// round 13
// baseline (speedup 1.0000x reference)
#include <cuda_runtime.h>
#include <cuda_bf16.h>

// STDP collapses because TE=1:
//   e_t = e_{t-1} - e_{t-1}/1 + (x_t q_t^T - p_t y_t^T) = x_t q_t^T - p_t y_t^T
// (the decay term is exactly zero), so the output is the LAST timestep's
// rank-2 outer product, with x,y the per-column filtered traces
//   x <- x + (p - x)*0.5  ==  x <- 0.5*x + 0.5*p.
// Closed form with truncation: x_T = sum_{k=0..H-1} s_k * 0.5^(H-k), where
// s_k = input[T-H+k]. H=16 => truncation error 2^-16 ~ 1.5e-5 abs (rel ~4e-5,
// far under the 1e-3 gate). The weighted sum has NO serial dependency, unlike
// the recurrence: 4 accumulators pipeline the 16 FMAs at issue rate and let
// ptxas front-batch all 16 loads (one latency exposure, MLP=16).
//
// Traces are recomputed PER BLOCK (no inter-block deps, single launch):
// 128 blocks = 16x8 tiles of 64 rows x 128 cols, 256 threads each.
//   entry:   Phase-B gmem operands (last pre/post rows) issued first.
//   Phase A: threads 0..63 -> x-trace (tile rows), 64..191 -> y-trace (cols).
//   Phase B: tile outer product, 8 coalesced float4 stores per thread (.cg).
//
// Shapes fixed by the problem: T=256, N_PRE=N_POST=1024.

#define HORIZON 16
#define TILE_R  64
#define TILE_C  128

__global__ void __launch_bounds__(256, 1)
stdp_tile_kernel(const float* __restrict__ pre,
                 const float* __restrict__ post,
                 float* __restrict__ out,
                 int T, int N)
{
    const int tid = threadIdx.x;
    const int bc  = blockIdx.x & 7;          // 8 column tiles
    const int br  = blockIdx.x >> 3;         // 16 row tiles
    const int r0  = br * TILE_R;
    const int c0  = bc * TILE_C;

    __shared__ float sx[TILE_R];             // x-trace for tile rows
    __shared__ float sy[TILE_C];             // y-trace for tile cols

    // ---- Issue Phase-B global loads FIRST (independent of the traces) ----
    const int cg = tid & 31;                 // 0..31 -> 4 cols each
    const int rb = tid >> 5;                 // 0..7  -> rows rb, rb+8, ..., rb+56
    const float* preLast  = pre  + (size_t)(T - 1) * N;
    const float* postLast = post + (size_t)(T - 1) * N;

    float4 q4 = __ldg(&reinterpret_cast<const float4*>(postLast + c0)[cg]);
    float  pi[8];
    #pragma unroll
    for (int r = 0; r < 8; ++r)
        pi[r] = __ldg(&preLast[r0 + rb + r * 8]);

    // ---------------- Phase A: weighted-sum trace (horizon 16) ----------------
    if (tid < TILE_R + TILE_C) {
        const bool isRow = tid < TILE_R;
        const float* src = isRow ? pre : post;
        const int col    = isRow ? (r0 + tid) : (c0 + tid - TILE_R);
        const float* base = src + (size_t)(T - HORIZON) * N + col;

        // x_T = sum_k s_k * 0.5^(HORIZON-k); weights are exact powers of two.
        // 4 independent accumulators -> no serial FMA chain.
        float a0 = 0.f, a1 = 0.f, a2 = 0.f, a3 = 0.f;
        #pragma unroll
        for (int k = 0; k < HORIZON; k += 4) {
            float w  = __uint_as_float((127u + k - HORIZON) << 23);  // 2^(k-HORIZON)
            a0 = fmaf(__ldg(base + (size_t)(k + 0) * N), w * 1.0f, a0);
            a1 = fmaf(__ldg(base + (size_t)(k + 1) * N), w * 2.0f, a1);
            a2 = fmaf(__ldg(base + (size_t)(k + 2) * N), w * 4.0f, a2);
            a3 = fmaf(__ldg(base + (size_t)(k + 3) * N), w * 8.0f, a3);
        }
        float acc = (a0 + a1) + (a2 + a3);
        if (isRow) sx[tid] = acc;
        else       sy[tid - TILE_R] = acc;
    }
    __syncthreads();

    // ---------------- Phase B: out[i][j] = x_i q_j - p_i y_j ----------------
    const int N4 = N >> 2;
    float4 y4 = reinterpret_cast<const float4*>(sy)[cg];

    float4* o = reinterpret_cast<float4*>(out);
    #pragma unroll
    for (int r = 0; r < 8; ++r) {
        int lr = rb + r * 8;                 // local row 0..63
        float xi = sx[lr];                   // smem broadcast across the warp
        float4 v;
        v.x = xi * q4.x - pi[r] * y4.x;
        v.y = xi * q4.y - pi[r] * y4.y;
        v.z = xi * q4.z - pi[r] * y4.z;
        v.w = xi * q4.w - pi[r] * y4.w;
        __stcg(&o[(size_t)(r0 + lr) * N4 + (c0 >> 2) + cg], v);
    }
}

extern "C" void kernel_launch(void* const* d_in, const int* in_sizes, int n_in,
                              void* d_out, int out_size)
{
    const float* pre  = (const float*)d_in[0];   // [T, N_pre]
    const float* post = (const float*)d_in[1];   // [T, N_post]
    float* out = (float*)d_out;                  // [N_pre, N_post]

    int N = 1;
    while ((long long)N * N < (long long)out_size) N <<= 1;   // -> 1024
    int T = in_sizes[0] / N;                                   // -> 256

    // 128 independent blocks (single wave), 256 threads, no cross-block deps.
    int grid = (N / TILE_R) * (N / TILE_C);                    // 16*8 = 128
    stdp_tile_kernel<<<grid, 256>>>(pre, post, out, T, N);
}

// round 15
// speedup vs baseline: 1.0386x; 1.0386x over previous
#include <cuda_runtime.h>
#include <cuda_bf16.h>

// STDP collapses because TE=1:
//   e_t = e_{t-1} - e_{t-1}/1 + (x_t q_t^T - p_t y_t^T) = x_t q_t^T - p_t y_t^T
// (the decay term is exactly zero), so the output is the LAST timestep's
// rank-2 outer product, with x,y the per-column filtered traces
//   x <- x + (p - x)*0.5.
// The homogeneous part scales by exactly 0.5/step: a 24-step horizon is exact
// to 2^-24 (~6e-8 abs) — cheap enough to recompute PER BLOCK, so there are no
// inter-block dependencies (single launch, no grid barrier).
//
// 128 blocks = 16x8 tiles of 64 rows x 128 cols, 256 threads each:
//   entry:   Phase-B gmem operands (last pre/post rows) are loaded FIRST so
//            their DRAM latency overlaps the trace chains.
//   Phase A: threads 0..63 -> x-trace for the tile's 64 rows,
//            threads 64..191 -> y-trace for its 128 cols (24 steps each).
//   Phase B: tile outer product, 8 float4 coalesced stores per thread.
//
// Converged configuration (R12 best): body is launch-ramp bound (occ = one
// block/SM, DRAM 0.5%, issue 14%); chain-removal and cache-op variants
// measured neutral, so the reference-op-order recurrence is kept for its
// 100x better rel_err margin.
//
// Shapes fixed by the problem: T=256, N_PRE=N_POST=1024.

#define HORIZON 24
#define TILE_R  64
#define TILE_C  128

__global__ void __launch_bounds__(256, 1)
stdp_tile_kernel(const float* __restrict__ pre,
                 const float* __restrict__ post,
                 float* __restrict__ out,
                 int T, int N)
{
    const int tid = threadIdx.x;
    const int bc  = blockIdx.x & 7;          // 8 column tiles
    const int br  = blockIdx.x >> 3;         // 16 row tiles
    const int r0  = br * TILE_R;
    const int c0  = bc * TILE_C;

    __shared__ float sx[TILE_R];             // x-trace for tile rows
    __shared__ float sy[TILE_C];             // y-trace for tile cols

    // ---- Issue Phase-B global loads FIRST (independent of the traces) ----
    const int cg = tid & 31;                 // 0..31 -> 4 cols each
    const int rb = tid >> 5;                 // 0..7  -> rows rb, rb+8, ..., rb+56
    const float* preLast  = pre  + (size_t)(T - 1) * N;
    const float* postLast = post + (size_t)(T - 1) * N;

    float4 q4 = __ldg(&reinterpret_cast<const float4*>(postLast + c0)[cg]);
    float  pi[8];
    #pragma unroll
    for (int r = 0; r < 8; ++r)
        pi[r] = __ldg(&preLast[r0 + rb + r * 8]);

    // ---------------- Phase A: 24-step traces for this tile ----------------
    if (tid < TILE_R + TILE_C) {
        const bool isRow = tid < TILE_R;
        const float* src = isRow ? pre : post;
        const int col    = isRow ? (r0 + tid) : (c0 + tid - TILE_R);

        const float* base = src + (size_t)(T - HORIZON) * N + col;
        float acc = 0.0f;
        #pragma unroll
        for (int k = 0; k < HORIZON; ++k) {
            float s = __ldg(base + (size_t)k * N);   // independent loads, batched
            acc = acc + (s - acc) * 0.5f;            // reference fp32 op order
        }
        if (isRow) sx[tid] = acc;
        else       sy[tid - TILE_R] = acc;
    }
    __syncthreads();

    // ---------------- Phase B: out[i][j] = x_i q_j - p_i y_j ----------------
    const int N4 = N >> 2;
    float4 y4 = reinterpret_cast<const float4*>(sy)[cg];

    float4* o = reinterpret_cast<float4*>(out);
    #pragma unroll
    for (int r = 0; r < 8; ++r) {
        int lr = rb + r * 8;                 // local row 0..63
        float xi = sx[lr];                   // smem broadcast across the warp
        float4 v;
        v.x = xi * q4.x - pi[r] * y4.x;
        v.y = xi * q4.y - pi[r] * y4.y;
        v.z = xi * q4.z - pi[r] * y4.z;
        v.w = xi * q4.w - pi[r] * y4.w;
        o[(size_t)(r0 + lr) * N4 + (c0 >> 2) + cg] = v;
    }
}

extern "C" void kernel_launch(void* const* d_in, const int* in_sizes, int n_in,
                              void* d_out, int out_size)
{
    const float* pre  = (const float*)d_in[0];   // [T, N_pre]
    const float* post = (const float*)d_in[1];   // [T, N_post]
    float* out = (float*)d_out;                  // [N_pre, N_post]

    int N = 1;
    while ((long long)N * N < (long long)out_size) N <<= 1;   // -> 1024
    int T = in_sizes[0] / N;                                   // -> 256

    // 128 independent blocks (single wave), 256 threads, no cross-block deps.
    int grid = (N / TILE_R) * (N / TILE_C);                    // 16*8 = 128
    stdp_tile_kernel<<<grid, 256>>>(pre, post, out, T, N);
}